// round 15
// baseline (speedup 1.0000x reference)
#include <cuda_runtime.h>
#include <cuda_fp16.h>
#include <math.h>
#include <stdint.h>

#define BB 32
#define NN 1024
#define DD 512
#define HH 8

// ---------------- scratch (device globals; no allocation allowed) ----------
__device__ float g_kh[(size_t)BB * HH * NN * DD / 2];   // kh half [BH][N][D]
__device__ float g_vh[(size_t)BB * HH * NN * DD / 2];   // vh half [BH][N][D] (natural)
__device__ float g_qh[(size_t)BB * HH * NN * DD / 2];   // qh half
__device__ float g_s [(size_t)BB * HH * NN * NN / 2];   // P half [BH][N][N]
__device__ float g_rs[(size_t)BB * HH * NN];            // row sums (float)
__device__ float g_att[(size_t)BB * NN * HH * DD];      // half: early rk/rv/rq, later att
__device__ float g_wr[(size_t)3 * HH * DD * DD / 2];    // half Wk,Wv,Wq
__device__ float g_wo[(size_t)HH * DD * DD / 2];        // half Wo permuted [e][h*D+d]

__device__ __forceinline__ uint32_t pkh2(__half2 h) { return *(uint32_t*)&h; }

#define MMA_F16(acc, af, bf)                                               \
    asm volatile(                                                          \
        "mma.sync.aligned.m16n8k16.row.col.f32.f16.f16.f32 "               \
        "{%0,%1,%2,%3}, {%4,%5,%6,%7}, {%8,%9}, {%0,%1,%2,%3};"            \
        : "+f"((acc)[0]), "+f"((acc)[1]), "+f"((acc)[2]), "+f"((acc)[3])   \
        : "r"((af)[0]), "r"((af)[1]), "r"((af)[2]), "r"((af)[3]),          \
          "r"((bf)[0]), "r"((bf)[1]))

#define LDSM4(r, addr)                                                     \
    asm volatile("ldmatrix.sync.aligned.m8n8.x4.shared.b16 "               \
                 "{%0,%1,%2,%3}, [%4];"                                    \
                 : "=r"((r)[0]), "=r"((r)[1]), "=r"((r)[2]), "=r"((r)[3])  \
                 : "r"(addr))

#define LDSM4T(r, addr)                                                    \
    asm volatile("ldmatrix.sync.aligned.m8n8.x4.trans.shared.b16 "         \
                 "{%0,%1,%2,%3}, [%4];"                                    \
                 : "=r"((r)[0]), "=r"((r)[1]), "=r"((r)[2]), "=r"((r)[3])  \
                 : "r"(addr))

// ---------------------------------------------------------------------------
// fp16 mma.sync GEMM (fp32 accum), WARP-PRIVATE staging: each of 4 warps
// (2x2, warp tile 64x64 within the 128x128 CTA tile) cp.asyncs its own
// operand halves into private smem (2 stages) and syncs ONLY via
// cp.async.wait_group + __syncwarp. No __syncthreads in the main loop:
// warps are fully independent streams (barrier skew eliminated).
// BNT=true: B stored [Nout][K] (NT).  BNT=false: B = V natural [K][Nout] (NN).
// EPI: 0 normal (alpha*acc + bias); OUT: 0 half store / 2 float store
//      1 P = half(exp(alpha*acc)); rowsums atomicAdd -> rsg
//      2 half(acc / rsg[row])
// All strides in half-element units. K multiple of 32.
// ---------------------------------------------------------------------------
#define WAHP 40                     // private A/B-NT pitch (32 data + 8 pad)
#define WAHT (64 * WAHP)            // 2560 halves per warp-stage
#define WVHP 72                     // private V pitch (64 data + 8 pad)
#define WVHT (32 * WVHP)            // 2304 halves per warp-stage
#define WSTG 2
// per-warp region: WSTG * (WAHT + WBT); total = 4 * that
#define SMEM_NT_H (4 * WSTG * (WAHT + WAHT) * 2)    // 81920 B
#define SMEM_AV_H (4 * WSTG * (WAHT + WVHT) * 2)    // 77824 B

// warp loads its own 64 rows x 32 halves (A or B-NT half-tile)
__device__ __forceinline__ void ldw_a(__half* dst, const __half* __restrict__ src,
                                      int ld, int row0, int k0, int lane) {
#pragma unroll
    for (int i = 0; i < 8; ++i) {
        int idx = lane + 32 * i;            // 0..255
        int r = idx >> 2;                   // 0..63
        int c = idx & 3;                    // 0..3 (16B chunks)
        uint32_t sa = (uint32_t)__cvta_generic_to_shared(dst + r * WAHP + c * 8);
        const __half* g = src + (long long)(row0 + r) * ld + k0 + c * 8;
        asm volatile("cp.async.cg.shared.global [%0], [%1], 16;" :: "r"(sa), "l"(g));
    }
}

// warp loads its own 32 k-rows x 64 e-halves of V
__device__ __forceinline__ void ldw_v(__half* dst, const __half* __restrict__ src,
                                      int ld, int e0, int k0, int lane) {
#pragma unroll
    for (int i = 0; i < 8; ++i) {
        int idx = lane + 32 * i;            // 0..255
        int r = idx >> 3;                   // 0..31
        int c = idx & 7;                    // 0..7 (16B chunks)
        uint32_t sa = (uint32_t)__cvta_generic_to_shared(dst + r * WVHP + c * 8);
        const __half* g = src + (long long)(k0 + r) * ld + e0 + c * 8;
        asm volatile("cp.async.cg.shared.global [%0], [%1], 16;" :: "r"(sa), "l"(g));
    }
}

template<int EPI, bool BNT, bool BIAS, int OUT>
__global__ __launch_bounds__(128, 2)
void gemm_h(const __half* __restrict__ A, const __half* __restrict__ B,
            const float* __restrict__ bias, void* __restrict__ Cv,
            float* __restrict__ rsg,
            int K, int lda, int ldb, int ldc,
            int aDiv, long long sA, int bMod, long long sB,
            int cDiv, long long sC1, int cMod, long long sC2,
            int biasMod, float alpha)
{
    extern __shared__ __half smh[];
    constexpr int WBT = BNT ? WAHT : WVHT;
    constexpr int WREG = WSTG * (WAHT + WBT);   // halves per warp region

    const int z = blockIdx.z;
    A += (long long)(z / aDiv) * sA;
    B += (long long)(z % bMod) * sB;
    const long long coff = (long long)(z / cDiv) * sC1 + (long long)(z % cMod) * sC2;
    __half* Ch = (__half*)Cv + coff;
    float*  Cf = (float*)Cv + coff;

    const int Nout = gridDim.x * 128;
    const int tid  = threadIdx.x;
    const int lane = tid & 31;
    const int wid  = tid >> 5;          // 0..3
    const int wm   = (wid & 1) * 64;
    const int wn   = (wid >> 1) * 64;
    const int m0   = blockIdx.y * 128;
    const int e0   = blockIdx.x * 128;
    const int gid  = lane >> 2;         // 0..7
    const int tg   = lane & 3;          // 0..3

    // this warp's private smem: [stage][A (WAHT) | B (WBT)]
    __half* wbase = smh + wid * WREG;
    const uint32_t wb = (uint32_t)__cvta_generic_to_shared(wbase);

    // ldmatrix per-lane byte offsets within a stage (A at 0, B at WAHT*2)
    uint32_t aoff[4];
#pragma unroll
    for (int i = 0; i < 4; ++i)
        aoff[i] = ((i * 16 + (lane & 15)) * WAHP + ((lane >> 4) & 1) * 8) * 2;
    uint32_t boff[4];
#pragma unroll
    for (int u = 0; u < 4; ++u) {
        if (BNT)
            boff[u] = (uint32_t)(WAHT * 2) +
                      ((u * 16 + ((lane >> 4) & 1) * 8 + (lane & 7)) * WAHP
                       + ((lane >> 3) & 1) * 8) * 2;
        else
            boff[u] = (uint32_t)(WAHT * 2) +
                      ((((lane >> 3) & 1) * 8 + (lane & 7)) * WVHP
                       + u * 16 + ((lane >> 4) & 1) * 8) * 2;
    }

    float acc[4][8][4];
#pragma unroll
    for (int i = 0; i < 4; i++)
#pragma unroll
        for (int j = 0; j < 8; j++)
#pragma unroll
            for (int t = 0; t < 4; t++) acc[i][j][t] = 0.0f;

    const int NC = K >> 5;
    // prologue: chunk 0 -> stage 0 (private)
    ldw_a(wbase, A, lda, m0 + wm, 0, lane);
    if (BNT) ldw_a(wbase + WAHT, B, ldb, e0 + wn, 0, lane);
    else     ldw_v(wbase + WAHT, B, ldb, e0 + wn, 0, lane);
    asm volatile("cp.async.commit_group;" ::: "memory");

    for (int c = 0; c < NC; ++c) {
        // prefetch chunk c+1 into the other stage (private; no CTA hazard)
        if (c + 1 < NC) {
            __half* st = wbase + ((c + 1) & 1) * (WAHT + WBT);
            ldw_a(st, A, lda, m0 + wm, (c + 1) * 32, lane);
            if (BNT) ldw_a(st + WAHT, B, ldb, e0 + wn, (c + 1) * 32, lane);
            else     ldw_v(st + WAHT, B, ldb, e0 + wn, (c + 1) * 32, lane);
        }
        asm volatile("cp.async.commit_group;" ::: "memory");
        asm volatile("cp.async.wait_group 1;" ::: "memory");
        __syncwarp();

        const uint32_t st = wb + (c & 1) * ((WAHT + WBT) * 2);

#pragma unroll
        for (int ks = 0; ks < 2; ++ks) {
            const int kk = ks * 16;
            uint32_t af[4][4];
#pragma unroll
            for (int i = 0; i < 4; ++i)
                LDSM4(af[i], st + aoff[i] + kk * 2);
#pragma unroll
            for (int u = 0; u < 4; ++u) {
                uint32_t bf[4];
                if (BNT) LDSM4(bf, st + boff[u] + kk * 2);
                else     LDSM4T(bf, st + boff[u] + kk * (WVHP * 2));
#pragma unroll
                for (int i = 0; i < 4; ++i) {
                    MMA_F16(acc[i][2 * u],     af[i], bf);
                    MMA_F16(acc[i][2 * u + 1], af[i], bf + 2);
                }
            }
        }
        __syncwarp();   // all lanes done reading stage before next overwrite
    }

    if (EPI == 0) {
        const float* bptr = BIAS ? (bias + (long long)(z % biasMod) * Nout) : nullptr;
#pragma unroll
        for (int i = 0; i < 4; ++i) {
            const int r0 = m0 + wm + i * 16 + gid;
#pragma unroll
            for (int j = 0; j < 8; ++j) {
                const int cc = e0 + wn + j * 8 + tg * 2;
#pragma unroll
                for (int hf = 0; hf < 2; ++hf) {
                    const int r = r0 + hf * 8;
                    float x = acc[i][j][hf * 2 + 0] * alpha;
                    float y = acc[i][j][hf * 2 + 1] * alpha;
                    if (BIAS) { x += bptr[cc]; y += bptr[cc + 1]; }
                    if (OUT == 0) {
                        *(__half2*)(Ch + (long long)r * ldc + cc) = __floats2half2_rn(x, y);
                    } else {
                        *(float2*)(Cf + (long long)r * ldc + cc) = make_float2(x, y);
                    }
                }
            }
        }
    } else if (EPI == 1) {
        float* rsp = rsg + (long long)z * NN;
#pragma unroll
        for (int i = 0; i < 4; ++i) {
            const int r0 = m0 + wm + i * 16 + gid;
            float s0 = 0.0f, s1 = 0.0f;
#pragma unroll
            for (int j = 0; j < 8; ++j) {
                const int cc = e0 + wn + j * 8 + tg * 2;
                __half2 p0 = __floats2half2_rn(__expf(acc[i][j][0] * alpha),
                                               __expf(acc[i][j][1] * alpha));
                __half2 p1 = __floats2half2_rn(__expf(acc[i][j][2] * alpha),
                                               __expf(acc[i][j][3] * alpha));
                *(__half2*)(Ch + (long long)r0 * ldc + cc)       = p0;
                *(__half2*)(Ch + (long long)(r0 + 8) * ldc + cc) = p1;
                float2 f0 = __half22float2(p0);
                float2 f1 = __half22float2(p1);
                s0 += f0.x + f0.y;
                s1 += f1.x + f1.y;
            }
            s0 += __shfl_xor_sync(0xffffffffu, s0, 1);
            s0 += __shfl_xor_sync(0xffffffffu, s0, 2);
            s1 += __shfl_xor_sync(0xffffffffu, s1, 1);
            s1 += __shfl_xor_sync(0xffffffffu, s1, 2);
            if (tg == 0) {
                atomicAdd(rsp + r0, s0);
                atomicAdd(rsp + r0 + 8, s1);
            }
        }
    } else {
        const float* rsp = rsg + (long long)z * NN;
#pragma unroll
        for (int i = 0; i < 4; ++i) {
            const int r0 = m0 + wm + i * 16 + gid;
            const float inv0 = 1.0f / rsp[r0];
            const float inv1 = 1.0f / rsp[r0 + 8];
#pragma unroll
            for (int j = 0; j < 8; ++j) {
                const int cc = e0 + wn + j * 8 + tg * 2;
                *(__half2*)(Ch + (long long)r0 * ldc + cc) =
                    __floats2half2_rn(acc[i][j][0] * inv0, acc[i][j][1] * inv0);
                *(__half2*)(Ch + (long long)(r0 + 8) * ldc + cc) =
                    __floats2half2_rn(acc[i][j][2] * inv1, acc[i][j][3] * inv1);
            }
        }
    }
}

// ---------------------------------------------------------------------------
__global__ void round3h_k(const float* __restrict__ x0, const float* __restrict__ x1,
                          const float* __restrict__ x2,
                          __half* __restrict__ y0, __half* __restrict__ y1,
                          __half* __restrict__ y2)
{
    const float* x = blockIdx.y == 0 ? x0 : (blockIdx.y == 1 ? x1 : x2);
    __half*      y = blockIdx.y == 0 ? y0 : (blockIdx.y == 1 ? y1 : y2);
    const long long i = ((long long)blockIdx.x * 256 + threadIdx.x) * 8;
    float4 v0 = *(const float4*)(x + i);
    float4 v1 = *(const float4*)(x + i + 4);
    uint4 u;
    u.x = pkh2(__floats2half2_rn(v0.x, v0.y));
    u.y = pkh2(__floats2half2_rn(v0.z, v0.w));
    u.z = pkh2(__floats2half2_rn(v1.x, v1.y));
    u.w = pkh2(__floats2half2_rn(v1.z, v1.w));
    *(uint4*)(y + i) = u;
}

// Permute Wo -> half: w2[e][h*D+d] = half(Wo[e][d*H+h])
__global__ void permwo_h(const float* __restrict__ Wo, __half* __restrict__ W2)
{
    const int idx = blockIdx.x * 256 + threadIdx.x;   // e*4096 + (h*512+d)
    const int e  = idx >> 12;
    const int kp = idx & 4095;
    const int h  = kp >> 9;
    const int d  = kp & 511;
    W2[idx] = __float2half_rn(Wo[(long long)e * (HH * DD) + d * HH + h]);
}

__global__ void zero_k(float* __restrict__ p)
{
    const long long i = ((long long)blockIdx.x * 256 + threadIdx.x) * 4;
    *(float4*)(p + i) = make_float4(0.f, 0.f, 0.f, 0.f);
}

// ---------------------------------------------------------------------------
extern "C" void kernel_launch(void* const* d_in, const int* in_sizes, int n_in,
                              void* d_out, int out_size)
{
    const float* k  = (const float*)d_in[0];
    const float* v  = (const float*)d_in[1];
    const float* q  = (const float*)d_in[2];
    const float* Wk = (const float*)d_in[3];
    const float* bk = (const float*)d_in[4];
    const float* Wv = (const float*)d_in[5];
    const float* bv = (const float*)d_in[6];
    const float* Wq = (const float*)d_in[7];
    const float* bq = (const float*)d_in[8];
    const float* Wo = (const float*)d_in[9];
    const float* bo = (const float*)d_in[10];
    float* out = (float*)d_out;

    void *khv, *vhv, *qhv, *sv, *rsv, *attv, *wrv, *wov;
    cudaGetSymbolAddress(&khv,  g_kh);
    cudaGetSymbolAddress(&vhv,  g_vh);
    cudaGetSymbolAddress(&qhv,  g_qh);
    cudaGetSymbolAddress(&sv,   g_s);
    cudaGetSymbolAddress(&rsv,  g_rs);
    cudaGetSymbolAddress(&attv, g_att);
    cudaGetSymbolAddress(&wrv,  g_wr);
    cudaGetSymbolAddress(&wov,  g_wo);

    __half* khh = (__half*)khv;
    __half* vhh = (__half*)vhv;
    __half* qhh = (__half*)qhv;
    __half* sh  = (__half*)sv;
    float*  rs  = (float*)rsv;
    __half* scratch = (__half*)attv;
    __half* wrh = (__half*)wrv;
    __half* w2h = (__half*)wov;

    cudaFuncSetAttribute((const void*)gemm_h<0, true, true, 0>,
                         cudaFuncAttributeMaxDynamicSharedMemorySize, SMEM_NT_H);
    cudaFuncSetAttribute((const void*)gemm_h<0, true, true, 2>,
                         cudaFuncAttributeMaxDynamicSharedMemorySize, SMEM_NT_H);
    cudaFuncSetAttribute((const void*)gemm_h<1, true, false, 0>,
                         cudaFuncAttributeMaxDynamicSharedMemorySize, SMEM_NT_H);
    cudaFuncSetAttribute((const void*)gemm_h<2, false, false, 0>,
                         cudaFuncAttributeMaxDynamicSharedMemorySize, SMEM_AV_H);

    const long long ND  = (long long)NN * DD;
    const long long WD  = (long long)DD * DD;
    const long long NNs = (long long)NN * NN;
    const long long BND = (long long)BB * NN * DD;
    const float alpha_s = 1.0f / sqrtf((float)DD);

    __half* rk = scratch;               // half scratch inside g_att region
    __half* rv = scratch + BND;
    __half* rq = scratch + 2 * BND;
    __half* atth = scratch;             // att reuses rk region (dead by then)
    __half* w0 = wrh;
    __half* w1 = wrh + HH * WD;
    __half* w2r = wrh + 2 * HH * WD;

    dim3 blk128(128), blk256(256);

    // pre-passes: fp32->fp16 rounds, Wo permute, rowsum zero
    round3h_k<<<dim3((int)(BND / 2048), 3), blk256>>>(k, v, q, rk, rv, rq);
    round3h_k<<<dim3((int)(HH * WD / 2048), 3), blk256>>>(Wk, Wv, Wq, w0, w1, w2r);
    permwo_h<<<(HH * DD * DD) / 256, blk256>>>(Wo, w2h);
    zero_k<<<(BB * HH * NN) / 1024, blk256>>>(rs);

    // projections: kh, qh, vh all natural half [BH][N][D]
    gemm_h<0, true, true, 0><<<dim3(4, 8, BB * HH), blk128, SMEM_NT_H>>>(
        rk, w0, bk, khh, nullptr, DD, DD, DD, DD,
        HH, ND, HH, WD, 1, ND, 1, 0, HH, 1.0f);
    gemm_h<0, true, true, 0><<<dim3(4, 8, BB * HH), blk128, SMEM_NT_H>>>(
        rv, w1, bv, vhh, nullptr, DD, DD, DD, DD,
        HH, ND, HH, WD, 1, ND, 1, 0, HH, 1.0f);
    gemm_h<0, true, true, 0><<<dim3(4, 8, BB * HH), blk128, SMEM_NT_H>>>(
        rq, w2r, bq, qhh, nullptr, DD, DD, DD, DD,
        HH, ND, HH, WD, 1, ND, 1, 0, HH, 1.0f);

    // scores + exp + rowsums: P = half(exp(scale * qh.kh^T))
    gemm_h<1, true, false, 0><<<dim3(8, 8, BB * HH), blk128, SMEM_NT_H>>>(
        qhh, khh, nullptr, sh, rs, DD, DD, DD, NN,
        1, ND, BB * HH, ND, 1, NNs, 1, 0, 1, alpha_s);

    // AV + divide-by-rowsum -> att half [B,N,H*D]
    gemm_h<2, false, false, 0><<<dim3(4, 8, BB * HH), blk128, SMEM_AV_H>>>(
        sh, vhh, nullptr, atth, rs, NN, NN, DD, HH * DD,
        1, NNs, BB * HH, ND, HH, (long long)NN * HH * DD, HH, DD, 1, 1.0f);

    // output projection: float out
    gemm_h<0, true, true, 2><<<dim3(4, 256, 1), blk128, SMEM_NT_H>>>(
        atth, w2h, bo, out, nullptr, HH * DD, HH * DD, HH * DD, DD,
        1, 0, 1, 0, 1, 0, 1, 0, 1, 1.0f);
}

// round 16
// speedup vs baseline: 1.2747x; 1.2747x over previous
#include <cuda_runtime.h>
#include <cuda_fp16.h>
#include <math.h>
#include <stdint.h>

#define BB 32
#define NN 1024
#define DD 512
#define HH 8

// ---------------- scratch (device globals; no allocation allowed) ----------
__device__ float g_kh[(size_t)BB * HH * NN * DD / 2];   // kh half [BH][N][D]
__device__ float g_vh[(size_t)BB * HH * NN * DD / 2];   // vh half [BH][N][D] (natural)
__device__ float g_qh[(size_t)BB * HH * NN * DD / 2];   // qh half
__device__ float g_s [(size_t)BB * HH * NN * NN / 2];   // P half [BH][N][N]
__device__ float g_rs[(size_t)BB * HH * NN];            // row sums (float)
__device__ float g_att[(size_t)BB * NN * HH * DD];      // half: early rk/rv/rq, later att
__device__ float g_wr[(size_t)3 * HH * DD * DD / 2];    // half Wk,Wv,Wq
__device__ float g_wo[(size_t)HH * DD * DD / 2];        // half Wo permuted [e][h*D+d]

__device__ __forceinline__ uint32_t pkh2(__half2 h) { return *(uint32_t*)&h; }

#define MMA_F16(acc, af, bf)                                               \
    asm volatile(                                                          \
        "mma.sync.aligned.m16n8k16.row.col.f32.f16.f16.f32 "               \
        "{%0,%1,%2,%3}, {%4,%5,%6,%7}, {%8,%9}, {%0,%1,%2,%3};"            \
        : "+f"((acc)[0]), "+f"((acc)[1]), "+f"((acc)[2]), "+f"((acc)[3])   \
        : "r"((af)[0]), "r"((af)[1]), "r"((af)[2]), "r"((af)[3]),          \
          "r"((bf)[0]), "r"((bf)[1]))

#define LDSM4(r, addr)                                                     \
    asm volatile("ldmatrix.sync.aligned.m8n8.x4.shared.b16 "               \
                 "{%0,%1,%2,%3}, [%4];"                                    \
                 : "=r"((r)[0]), "=r"((r)[1]), "=r"((r)[2]), "=r"((r)[3])  \
                 : "r"(addr))

#define LDSM4T(r, addr)                                                    \
    asm volatile("ldmatrix.sync.aligned.m8n8.x4.trans.shared.b16 "         \
                 "{%0,%1,%2,%3}, [%4];"                                    \
                 : "=r"((r)[0]), "=r"((r)[1]), "=r"((r)[2]), "=r"((r)[3])  \
                 : "r"(addr))

// ---------------------------------------------------------------------------
// fp16 mma.sync GEMM (fp32 accum). 128x128 CTA tile, 4 warps (2x2),
// warp tile 64x64. K-chunk 32 (2 x k16), 3-stage cp.async (wait 1),
// ldmatrix fragments. 2 CTAs/SM.  [R10 certified-optimum configuration]
// BNT=true: B stored [Nout][K] (NT).  BNT=false: B = V natural [K][Nout] (NN).
// EPI: 0 normal (alpha*acc + bias); OUT: 0 half store / 2 float store
//      1 P = half(exp(alpha*acc)); rowsums atomicAdd -> rsg
//      2 half(acc / rsg[row])
// All strides in half-element units.
// ---------------------------------------------------------------------------
#define AHP 40                      // A/B-NT tile pitch in halves
#define AHT (128 * AHP)             // 5120 halves / stage
#define VHP 136                     // V tile pitch in halves (128 data + 8 pad)
#define VHT (32 * VHP)              // 4352 halves / stage
#define NSTG 3
#define SMEM_NT_H (NSTG * (AHT + AHT) * 2)     // 61440 B
#define SMEM_AV_H (NSTG * (AHT + VHT) * 2)     // 56832 B

__device__ __forceinline__ void ldg_h(__half* dst, const __half* __restrict__ src,
                                      int ld, int row0, int k0, int tid) {
#pragma unroll
    for (int i = 0; i < 4; ++i) {
        int idx = tid + 128 * i;            // 0..511
        int r = idx >> 2;                   // 0..127
        int c = idx & 3;                    // 0..3 (16B = 8-half chunks)
        uint32_t sa = (uint32_t)__cvta_generic_to_shared(dst + r * AHP + c * 8);
        const __half* g = src + (long long)(row0 + r) * ld + k0 + c * 8;
        asm volatile("cp.async.cg.shared.global [%0], [%1], 16;" :: "r"(sa), "l"(g));
    }
}

// V tile: 32 k-rows x 128 e-halves, natural layout
__device__ __forceinline__ void ldg_hv(__half* dst, const __half* __restrict__ src,
                                       int ld, int e0, int k0, int tid) {
#pragma unroll
    for (int i = 0; i < 4; ++i) {
        int idx = tid + 128 * i;            // 0..511
        int r = idx >> 4;                   // 0..31
        int c = idx & 15;                   // 0..15 (8-half chunks)
        uint32_t sa = (uint32_t)__cvta_generic_to_shared(dst + r * VHP + c * 8);
        const __half* g = src + (long long)(k0 + r) * ld + e0 + c * 8;
        asm volatile("cp.async.cg.shared.global [%0], [%1], 16;" :: "r"(sa), "l"(g));
    }
}

template<int EPI, bool BNT, bool BIAS, int OUT>
__global__ __launch_bounds__(128, 2)
void gemm_h(const __half* __restrict__ A, const __half* __restrict__ B,
            const float* __restrict__ bias, void* __restrict__ Cv,
            float* __restrict__ rsg,
            int K, int lda, int ldb, int ldc,
            int aDiv, long long sA, int bMod, long long sB,
            int cDiv, long long sC1, int cMod, long long sC2,
            int biasMod, float alpha)
{
    extern __shared__ __half smh[];
    constexpr int BT = BNT ? AHT : VHT;
    __half* As = smh;                  // [NSTG][AHT]
    __half* Bs = smh + NSTG * AHT;     // [NSTG][BT]
    const uint32_t abase = (uint32_t)__cvta_generic_to_shared(As);
    const uint32_t bbase = (uint32_t)__cvta_generic_to_shared(Bs);

    const int z = blockIdx.z;
    A += (long long)(z / aDiv) * sA;
    B += (long long)(z % bMod) * sB;
    const long long coff = (long long)(z / cDiv) * sC1 + (long long)(z % cMod) * sC2;
    __half* Ch = (__half*)Cv + coff;
    float*  Cf = (float*)Cv + coff;

    const int Nout = gridDim.x * 128;
    const int tid  = threadIdx.x;
    const int lane = tid & 31;
    const int wid  = tid >> 5;          // 0..3
    const int wm   = (wid & 1) * 64;
    const int wn   = (wid >> 1) * 64;
    const int m0   = blockIdx.y * 128;
    const int e0   = blockIdx.x * 128;
    const int gid  = lane >> 2;         // 0..7
    const int tg   = lane & 3;          // 0..3

    // ldmatrix per-lane byte offsets (relative to stage base)
    uint32_t aoff[4];
#pragma unroll
    for (int i = 0; i < 4; ++i)
        aoff[i] = ((wm + i * 16 + (lane & 15)) * AHP + ((lane >> 4) & 1) * 8) * 2;
    uint32_t boff[4];
#pragma unroll
    for (int u = 0; u < 4; ++u) {
        if (BNT)
            boff[u] = ((wn + u * 16 + ((lane >> 4) & 1) * 8 + (lane & 7)) * AHP
                       + ((lane >> 3) & 1) * 8) * 2;
        else
            boff[u] = ((((lane >> 3) & 1) * 8 + (lane & 7)) * VHP
                       + wn + u * 16 + ((lane >> 4) & 1) * 8) * 2;
    }

    float acc[4][8][4];
#pragma unroll
    for (int i = 0; i < 4; i++)
#pragma unroll
        for (int j = 0; j < 8; j++)
#pragma unroll
            for (int t = 0; t < 4; t++) acc[i][j][t] = 0.0f;

    const int NC = K >> 5;
    // prologue: chunks 0,1 -> stages 0,1
    ldg_h(As, A, lda, m0, 0, tid);
    if (BNT) ldg_h(Bs, B, ldb, e0, 0, tid);
    else     ldg_hv(Bs, B, ldb, e0, 0, tid);
    asm volatile("cp.async.commit_group;" ::: "memory");
    ldg_h(As + AHT, A, lda, m0, 32, tid);
    if (BNT) ldg_h(Bs + AHT, B, ldb, e0, 32, tid);
    else     ldg_hv(Bs + VHT, B, ldb, e0, 32, tid);
    asm volatile("cp.async.commit_group;" ::: "memory");

    int s = 0, sp = 2;                  // compute stage, prefetch stage
    for (int c = 0; c < NC; ++c) {
        asm volatile("cp.async.wait_group 1;" ::: "memory");
        __syncthreads();

        if (c + 2 < NC) {
            ldg_h(As + sp * AHT, A, lda, m0, (c + 2) * 32, tid);
            if (BNT) ldg_h(Bs + sp * AHT, B, ldb, e0, (c + 2) * 32, tid);
            else     ldg_hv(Bs + sp * VHT, B, ldb, e0, (c + 2) * 32, tid);
        }
        asm volatile("cp.async.commit_group;" ::: "memory");

        const uint32_t as = abase + s * (AHT * 2);
        const uint32_t bsd = bbase + s * (BT * 2);

#pragma unroll
        for (int ks = 0; ks < 2; ++ks) {
            const int kk = ks * 16;
            uint32_t af[4][4];
#pragma unroll
            for (int i = 0; i < 4; ++i)
                LDSM4(af[i], as + aoff[i] + kk * 2);
#pragma unroll
            for (int u = 0; u < 4; ++u) {
                uint32_t bf[4];
                if (BNT) LDSM4(bf, bsd + boff[u] + kk * 2);
                else     LDSM4T(bf, bsd + boff[u] + kk * (VHP * 2));
#pragma unroll
                for (int i = 0; i < 4; ++i) {
                    MMA_F16(acc[i][2 * u],     af[i], bf);
                    MMA_F16(acc[i][2 * u + 1], af[i], bf + 2);
                }
            }
        }
        s = (s + 1 == NSTG) ? 0 : s + 1;
        sp = (sp + 1 == NSTG) ? 0 : sp + 1;
    }

    if (EPI == 0) {
        const float* bptr = BIAS ? (bias + (long long)(z % biasMod) * Nout) : nullptr;
#pragma unroll
        for (int i = 0; i < 4; ++i) {
            const int r0 = m0 + wm + i * 16 + gid;
#pragma unroll
            for (int j = 0; j < 8; ++j) {
                const int cc = e0 + wn + j * 8 + tg * 2;
#pragma unroll
                for (int hf = 0; hf < 2; ++hf) {
                    const int r = r0 + hf * 8;
                    float x = acc[i][j][hf * 2 + 0] * alpha;
                    float y = acc[i][j][hf * 2 + 1] * alpha;
                    if (BIAS) { x += bptr[cc]; y += bptr[cc + 1]; }
                    if (OUT == 0) {
                        *(__half2*)(Ch + (long long)r * ldc + cc) = __floats2half2_rn(x, y);
                    } else {
                        *(float2*)(Cf + (long long)r * ldc + cc) = make_float2(x, y);
                    }
                }
            }
        }
    } else if (EPI == 1) {
        float* rsp = rsg + (long long)z * NN;
#pragma unroll
        for (int i = 0; i < 4; ++i) {
            const int r0 = m0 + wm + i * 16 + gid;
            float s0 = 0.0f, s1 = 0.0f;
#pragma unroll
            for (int j = 0; j < 8; ++j) {
                const int cc = e0 + wn + j * 8 + tg * 2;
                __half2 p0 = __floats2half2_rn(__expf(acc[i][j][0] * alpha),
                                               __expf(acc[i][j][1] * alpha));
                __half2 p1 = __floats2half2_rn(__expf(acc[i][j][2] * alpha),
                                               __expf(acc[i][j][3] * alpha));
                *(__half2*)(Ch + (long long)r0 * ldc + cc)       = p0;
                *(__half2*)(Ch + (long long)(r0 + 8) * ldc + cc) = p1;
                float2 f0 = __half22float2(p0);
                float2 f1 = __half22float2(p1);
                s0 += f0.x + f0.y;
                s1 += f1.x + f1.y;
            }
            s0 += __shfl_xor_sync(0xffffffffu, s0, 1);
            s0 += __shfl_xor_sync(0xffffffffu, s0, 2);
            s1 += __shfl_xor_sync(0xffffffffu, s1, 1);
            s1 += __shfl_xor_sync(0xffffffffu, s1, 2);
            if (tg == 0) {
                atomicAdd(rsp + r0, s0);
                atomicAdd(rsp + r0 + 8, s1);
            }
        }
    } else {
        const float* rsp = rsg + (long long)z * NN;
#pragma unroll
        for (int i = 0; i < 4; ++i) {
            const int r0 = m0 + wm + i * 16 + gid;
            const float inv0 = 1.0f / rsp[r0];
            const float inv1 = 1.0f / rsp[r0 + 8];
#pragma unroll
            for (int j = 0; j < 8; ++j) {
                const int cc = e0 + wn + j * 8 + tg * 2;
                *(__half2*)(Ch + (long long)r0 * ldc + cc) =
                    __floats2half2_rn(acc[i][j][0] * inv0, acc[i][j][1] * inv0);
                *(__half2*)(Ch + (long long)(r0 + 8) * ldc + cc) =
                    __floats2half2_rn(acc[i][j][2] * inv1, acc[i][j][3] * inv1);
            }
        }
    }
}

// ---------------------------------------------------------------------------
__global__ void round3h_k(const float* __restrict__ x0, const float* __restrict__ x1,
                          const float* __restrict__ x2,
                          __half* __restrict__ y0, __half* __restrict__ y1,
                          __half* __restrict__ y2)
{
    const float* x = blockIdx.y == 0 ? x0 : (blockIdx.y == 1 ? x1 : x2);
    __half*      y = blockIdx.y == 0 ? y0 : (blockIdx.y == 1 ? y1 : y2);
    const long long i = ((long long)blockIdx.x * 256 + threadIdx.x) * 8;
    float4 v0 = *(const float4*)(x + i);
    float4 v1 = *(const float4*)(x + i + 4);
    uint4 u;
    u.x = pkh2(__floats2half2_rn(v0.x, v0.y));
    u.y = pkh2(__floats2half2_rn(v0.z, v0.w));
    u.z = pkh2(__floats2half2_rn(v1.x, v1.y));
    u.w = pkh2(__floats2half2_rn(v1.z, v1.w));
    *(uint4*)(y + i) = u;
}

// Permute Wo -> half: w2[e][h*D+d] = half(Wo[e][d*H+h])
__global__ void permwo_h(const float* __restrict__ Wo, __half* __restrict__ W2)
{
    const int idx = blockIdx.x * 256 + threadIdx.x;   // e*4096 + (h*512+d)
    const int e  = idx >> 12;
    const int kp = idx & 4095;
    const int h  = kp >> 9;
    const int d  = kp & 511;
    W2[idx] = __float2half_rn(Wo[(long long)e * (HH * DD) + d * HH + h]);
}

__global__ void zero_k(float* __restrict__ p)
{
    const long long i = ((long long)blockIdx.x * 256 + threadIdx.x) * 4;
    *(float4*)(p + i) = make_float4(0.f, 0.f, 0.f, 0.f);
}

// ---------------------------------------------------------------------------
extern "C" void kernel_launch(void* const* d_in, const int* in_sizes, int n_in,
                              void* d_out, int out_size)
{
    const float* k  = (const float*)d_in[0];
    const float* v  = (const float*)d_in[1];
    const float* q  = (const float*)d_in[2];
    const float* Wk = (const float*)d_in[3];
    const float* bk = (const float*)d_in[4];
    const float* Wv = (const float*)d_in[5];
    const float* bv = (const float*)d_in[6];
    const float* Wq = (const float*)d_in[7];
    const float* bq = (const float*)d_in[8];
    const float* Wo = (const float*)d_in[9];
    const float* bo = (const float*)d_in[10];
    float* out = (float*)d_out;

    void *khv, *vhv, *qhv, *sv, *rsv, *attv, *wrv, *wov;
    cudaGetSymbolAddress(&khv,  g_kh);
    cudaGetSymbolAddress(&vhv,  g_vh);
    cudaGetSymbolAddress(&qhv,  g_qh);
    cudaGetSymbolAddress(&sv,   g_s);
    cudaGetSymbolAddress(&rsv,  g_rs);
    cudaGetSymbolAddress(&attv, g_att);
    cudaGetSymbolAddress(&wrv,  g_wr);
    cudaGetSymbolAddress(&wov,  g_wo);

    __half* khh = (__half*)khv;
    __half* vhh = (__half*)vhv;
    __half* qhh = (__half*)qhv;
    __half* sh  = (__half*)sv;
    float*  rs  = (float*)rsv;
    __half* scratch = (__half*)attv;
    __half* wrh = (__half*)wrv;
    __half* w2h = (__half*)wov;

    cudaFuncSetAttribute((const void*)gemm_h<0, true, true, 0>,
                         cudaFuncAttributeMaxDynamicSharedMemorySize, SMEM_NT_H);
    cudaFuncSetAttribute((const void*)gemm_h<0, true, true, 2>,
                         cudaFuncAttributeMaxDynamicSharedMemorySize, SMEM_NT_H);
    cudaFuncSetAttribute((const void*)gemm_h<1, true, false, 0>,
                         cudaFuncAttributeMaxDynamicSharedMemorySize, SMEM_NT_H);
    cudaFuncSetAttribute((const void*)gemm_h<2, false, false, 0>,
                         cudaFuncAttributeMaxDynamicSharedMemorySize, SMEM_AV_H);

    const long long ND  = (long long)NN * DD;
    const long long WD  = (long long)DD * DD;
    const long long NNs = (long long)NN * NN;
    const long long BND = (long long)BB * NN * DD;
    const float alpha_s = 1.0f / sqrtf((float)DD);

    __half* rk = scratch;               // half scratch inside g_att region
    __half* rv = scratch + BND;
    __half* rq = scratch + 2 * BND;
    __half* atth = scratch;             // att reuses rk region (dead by then)
    __half* w0 = wrh;
    __half* w1 = wrh + HH * WD;
    __half* w2r = wrh + 2 * HH * WD;

    dim3 blk128(128), blk256(256);

    // pre-passes: fp32->fp16 rounds, Wo permute, rowsum zero
    round3h_k<<<dim3((int)(BND / 2048), 3), blk256>>>(k, v, q, rk, rv, rq);
    round3h_k<<<dim3((int)(HH * WD / 2048), 3), blk256>>>(Wk, Wv, Wq, w0, w1, w2r);
    permwo_h<<<(HH * DD * DD) / 256, blk256>>>(Wo, w2h);
    zero_k<<<(BB * HH * NN) / 1024, blk256>>>(rs);

    // projections: kh, qh, vh all natural half [BH][N][D]
    gemm_h<0, true, true, 0><<<dim3(4, 8, BB * HH), blk128, SMEM_NT_H>>>(
        rk, w0, bk, khh, nullptr, DD, DD, DD, DD,
        HH, ND, HH, WD, 1, ND, 1, 0, HH, 1.0f);
    gemm_h<0, true, true, 0><<<dim3(4, 8, BB * HH), blk128, SMEM_NT_H>>>(
        rv, w1, bv, vhh, nullptr, DD, DD, DD, DD,
        HH, ND, HH, WD, 1, ND, 1, 0, HH, 1.0f);
    gemm_h<0, true, true, 0><<<dim3(4, 8, BB * HH), blk128, SMEM_NT_H>>>(
        rq, w2r, bq, qhh, nullptr, DD, DD, DD, DD,
        HH, ND, HH, WD, 1, ND, 1, 0, HH, 1.0f);

    // scores + exp + rowsums: P = half(exp(scale * qh.kh^T))
    gemm_h<1, true, false, 0><<<dim3(8, 8, BB * HH), blk128, SMEM_NT_H>>>(
        qhh, khh, nullptr, sh, rs, DD, DD, DD, NN,
        1, ND, BB * HH, ND, 1, NNs, 1, 0, 1, alpha_s);

    // AV + divide-by-rowsum -> att half [B,N,H*D]
    gemm_h<2, false, false, 0><<<dim3(4, 8, BB * HH), blk128, SMEM_AV_H>>>(
        sh, vhh, nullptr, atth, rs, NN, NN, DD, HH * DD,
        1, NNs, BB * HH, ND, HH, (long long)NN * HH * DD, HH, DD, 1, 1.0f);

    // output projection: float out
    gemm_h<0, true, true, 2><<<dim3(4, 256, 1), blk128, SMEM_NT_H>>>(
        atth, w2h, bo, out, nullptr, HH * DD, HH * DD, HH * DD, DD,
        1, 0, 1, 0, 1, 0, 1, 0, 1, 1.0f);
}